// round 1
// baseline (speedup 1.0000x reference)
#include <cuda_runtime.h>
#include <cstdint>
#include <cstddef>

// Problem constants (fixed by the dataset)
#define T_STEPS 512
#define BATCH   128
#define DIN     512
#define HID     512
#define G4      2048   // 4*HID

// ---------------------------------------------------------------------------
// Device-global scratch (allocation-free rule: __device__ arrays only).
// g_xg: precomputed input projections, [T, B, 4H] fp32  (512 MB)
// g_bar / g_exit: grid-barrier state; reset by the last-exiting block so every
// graph replay starts from zeroed state.
// ---------------------------------------------------------------------------
__device__ float        g_xg[(size_t)T_STEPS * BATCH * G4];
__device__ unsigned int g_bar[T_STEPS];
__device__ unsigned int g_exit;

// ---------------------------------------------------------------------------
// tf32 helpers
// ---------------------------------------------------------------------------
__device__ __forceinline__ uint32_t f2tf(float f) {
    uint32_t u;
    asm("cvt.rna.tf32.f32 %0, %1;" : "=r"(u) : "f"(f));
    return u;
}

// D += A(16x8, tf32) * B(8x8, tf32), fp32 accum. Standard m16n8k8 layout.
__device__ __forceinline__ void mma_tf32(float* d,
    uint32_t a0, uint32_t a1, uint32_t a2, uint32_t a3,
    uint32_t b0, uint32_t b1)
{
    asm volatile(
        "mma.sync.aligned.m16n8k8.row.col.f32.tf32.tf32.f32 "
        "{%0,%1,%2,%3}, {%4,%5,%6,%7}, {%8,%9}, {%0,%1,%2,%3};\n"
        : "+f"(d[0]), "+f"(d[1]), "+f"(d[2]), "+f"(d[3])
        : "r"(a0), "r"(a1), "r"(a2), "r"(a3), "r"(b0), "r"(b1));
}

__device__ __forceinline__ float sigmoidf_(float x) {
    return 1.0f / (1.0f + __expf(-x));
}

// ===========================================================================
// Phase A: xg[m][n] = sum_k x[m][k] * Wx[n][k] + bx[n] + bh[n]
//   M = T*B = 65536, N = 2048, K = 512.
//   Block tile 128x128, BK=16, 256 threads, warp tile 32x64.
//   SMEM tiles stored as tf32 with padded stride 20 (conflict-free frag LDS).
// ===========================================================================
__global__ __launch_bounds__(256, 2) void gemm_xg_kernel(
    const float* __restrict__ x,
    const float* __restrict__ Wx,
    const float* __restrict__ bxp,
    const float* __restrict__ bhp)
{
    __shared__ uint32_t As[128 * 20];
    __shared__ uint32_t Bs[128 * 20];

    const int tid  = threadIdx.x;
    const int bn   = blockIdx.x * 128;   // N base
    const int bm   = blockIdx.y * 128;   // M base
    const int warp = tid >> 5;
    const int lane = tid & 31;
    const int wm   = (warp & 3) * 32;    // warp row offset (4 warps over M)
    const int wn   = (warp >> 2) * 64;   // warp col offset (2 warps over N)
    const int g    = lane >> 2;          // group 0..7
    const int t    = lane & 3;           // tid-in-group 0..3

    float acc[2][8][4];
#pragma unroll
    for (int i = 0; i < 2; i++)
#pragma unroll
        for (int j = 0; j < 8; j++)
#pragma unroll
            for (int q = 0; q < 4; q++) acc[i][j][q] = 0.0f;

    for (int k0 = 0; k0 < DIN; k0 += 16) {
        // ---- load tiles (each thread: 2 float4 of A, 2 float4 of B) ----
#pragma unroll
        for (int i = 0; i < 2; i++) {
            int id = i * 256 + tid;        // 0..511 float4 slots
            int r  = id >> 2;              // 0..127
            int c4 = id & 3;               // 0..3
            float4 va = *(const float4*)(x + (size_t)(bm + r) * DIN + k0 + c4 * 4);
            uint4  ua;
            ua.x = f2tf(va.x); ua.y = f2tf(va.y); ua.z = f2tf(va.z); ua.w = f2tf(va.w);
            *(uint4*)(As + r * 20 + c4 * 4) = ua;

            float4 vb = *(const float4*)(Wx + (size_t)(bn + r) * DIN + k0 + c4 * 4);
            uint4  ub;
            ub.x = f2tf(vb.x); ub.y = f2tf(vb.y); ub.z = f2tf(vb.z); ub.w = f2tf(vb.w);
            *(uint4*)(Bs + r * 20 + c4 * 4) = ub;
        }
        __syncthreads();

#pragma unroll
        for (int kk = 0; kk < 2; kk++) {
            uint32_t a[2][4], b[8][2];
#pragma unroll
            for (int mt = 0; mt < 2; mt++) {
                int row = wm + mt * 16;
                a[mt][0] = As[(row + g    ) * 20 + kk * 8 + t];
                a[mt][1] = As[(row + g + 8) * 20 + kk * 8 + t];
                a[mt][2] = As[(row + g    ) * 20 + kk * 8 + t + 4];
                a[mt][3] = As[(row + g + 8) * 20 + kk * 8 + t + 4];
            }
#pragma unroll
            for (int nt = 0; nt < 8; nt++) {
                int col = wn + nt * 8 + g;
                b[nt][0] = Bs[col * 20 + kk * 8 + t];
                b[nt][1] = Bs[col * 20 + kk * 8 + t + 4];
            }
#pragma unroll
            for (int mt = 0; mt < 2; mt++)
#pragma unroll
                for (int nt = 0; nt < 8; nt++)
                    mma_tf32(acc[mt][nt],
                             a[mt][0], a[mt][1], a[mt][2], a[mt][3],
                             b[nt][0], b[nt][1]);
        }
        __syncthreads();
    }

    // ---- epilogue: add biases, store to g_xg ----
#pragma unroll
    for (int mt = 0; mt < 2; mt++) {
        int row0 = bm + wm + mt * 16 + g;
#pragma unroll
        for (int nt = 0; nt < 8; nt++) {
            int col = bn + wn + nt * 8 + 2 * t;
            float bias0 = bxp[col]     + bhp[col];
            float bias1 = bxp[col + 1] + bhp[col + 1];
            float2 v0 = make_float2(acc[mt][nt][0] + bias0, acc[mt][nt][1] + bias1);
            float2 v1 = make_float2(acc[mt][nt][2] + bias0, acc[mt][nt][3] + bias1);
            *(float2*)(g_xg + (size_t)row0 * G4 + col)       = v0;
            *(float2*)(g_xg + (size_t)(row0 + 8) * G4 + col) = v1;
        }
    }
}

// ===========================================================================
// Phase B: persistent recurrent kernel.
//   grid = 128 blocks (4 batch-groups x 32 j-groups), 256 threads each.
//   Block owns batch rows [bi*32, bi*32+32) and h columns [bj*16, bj*16+16),
//   i.e. gate columns {g*512 + j : g in 0..3}. c lives in SMEM; h round-trips
//   through d_out (out[t] IS h_t).
//   Per step: load h tile (32x512) -> SMEM (tf32), 32x64x512 tf32 GEMM vs the
//   resident Wh slice, gates -> SMEM, elementwise, store h to out[t],
//   grid barrier.
// SMEM layout (dynamic, words):
//   Whs[64*516] | Hs[32*516] | Gs(32*66 floats) | Cs(512 floats)
// ===========================================================================
#define WHS_WORDS (64 * 516)
#define HS_WORDS  (32 * 516)
#define GS_FLOATS (32 * 66)
#define CS_FLOATS (512)
#define SMEM_B_BYTES ((WHS_WORDS + HS_WORDS + GS_FLOATS + CS_FLOATS) * 4)

__global__ __launch_bounds__(256, 1) void lstm_rec_kernel(
    const float* __restrict__ Wh,
    float* __restrict__ out)
{
    extern __shared__ uint32_t sm[];
    uint32_t* Whs = sm;                       // [64][516] tf32
    uint32_t* Hs  = sm + WHS_WORDS;           // [32][516] tf32
    float*    Gs  = (float*)(sm + WHS_WORDS + HS_WORDS);  // [32][66]
    float*    Cs  = Gs + GS_FLOATS;           // [32][16] cell state

    const int tid  = threadIdx.x;
    const int warp = tid >> 5;
    const int lane = tid & 31;
    const int g    = lane >> 2;
    const int t    = lane & 3;

    const int bi = blockIdx.x >> 5;   // 0..3  batch group
    const int bj = blockIdx.x & 31;   // 0..31 j group
    const int b0 = bi * 32;
    const int j0 = bj * 16;

    // ---- one-time: Wh slice -> SMEM (tf32), c = 0 ----
    for (int idx = tid; idx < 64 * 512; idx += 256) {
        int c = idx >> 9;            // 0..63 local gate column
        int k = idx & 511;
        int gcol = (c >> 4) * HID + j0 + (c & 15);   // global gate column
        Whs[c * 516 + k] = f2tf(Wh[(size_t)gcol * HID + k]);
    }
    for (int i = tid; i < CS_FLOATS; i += 256) Cs[i] = 0.0f;
    __syncthreads();

    const int mt    = warp & 1;      // 0..1 : 16-row m-tile
    const int npair = warp >> 1;     // 0..3 : pair of 8-col n-tiles

    // elementwise assignment: thread handles (er, ej) and (er, ej+1)
    const int e0 = tid * 2;
    const int er = e0 >> 4;          // 0..31 local batch row
    const int ej = e0 & 15;          // even local j

    const uint32_t* Arow0 = Hs + (mt * 16 + g) * 516;
    const uint32_t* Arow1 = Hs + (mt * 16 + g + 8) * 516;
    const uint32_t* Brow0 = Whs + (npair * 16 + g) * 516;       // ntile 2*npair
    const uint32_t* Brow1 = Whs + (npair * 16 + 8 + g) * 516;   // ntile 2*npair+1

    for (int ts = 0; ts < T_STEPS; ts++) {
        // ---- prefetch xg for this thread's 2 elements (hidden under mma) ----
        const float* xgp = g_xg + ((size_t)ts * BATCH + b0 + er) * G4 + j0;
        float xi0 = xgp[ej],            xi1 = xgp[ej + 1];
        float xf0 = xgp[HID + ej],      xf1 = xgp[HID + ej + 1];
        float xg0 = xgp[2 * HID + ej],  xg1 = xgp[2 * HID + ej + 1];
        float xo0 = xgp[3 * HID + ej],  xo1 = xgp[3 * HID + ej + 1];

        if (ts > 0) {
            // ---- load h_{t-1} tile -> SMEM (tf32) ----
            const float* hsrc = out + (size_t)(ts - 1) * (BATCH * HID) + (size_t)b0 * HID;
#pragma unroll
            for (int i = 0; i < 16; i++) {
                int id = i * 256 + tid;        // 0..4095 float4 slots
                int r  = id >> 7;              // 0..31
                int k4 = id & 127;             // 0..127
                float4 v = *(const float4*)(hsrc + r * HID + k4 * 4);
                uint4  u;
                u.x = f2tf(v.x); u.y = f2tf(v.y); u.z = f2tf(v.z); u.w = f2tf(v.w);
                *(uint4*)(Hs + r * 516 + k4 * 4) = u;
            }
            __syncthreads();

            // ---- 32x64x512 tf32 GEMM: even/odd-k accumulator pairs for ILP ----
            float ac0[4] = {0.f, 0.f, 0.f, 0.f};
            float ac1[4] = {0.f, 0.f, 0.f, 0.f};
            float bc0[4] = {0.f, 0.f, 0.f, 0.f};
            float bc1[4] = {0.f, 0.f, 0.f, 0.f};

#pragma unroll 2
            for (int kk = 0; kk < 64; kk += 2) {
                int kb = kk * 8 + t;
                {
                    uint32_t a0 = Arow0[kb], a1 = Arow1[kb];
                    uint32_t a2 = Arow0[kb + 4], a3 = Arow1[kb + 4];
                    uint32_t p0 = Brow0[kb], p1 = Brow0[kb + 4];
                    uint32_t q0 = Brow1[kb], q1 = Brow1[kb + 4];
                    mma_tf32(ac0, a0, a1, a2, a3, p0, p1);
                    mma_tf32(ac1, a0, a1, a2, a3, q0, q1);
                }
                kb += 8;
                {
                    uint32_t a0 = Arow0[kb], a1 = Arow1[kb];
                    uint32_t a2 = Arow0[kb + 4], a3 = Arow1[kb + 4];
                    uint32_t p0 = Brow0[kb], p1 = Brow0[kb + 4];
                    uint32_t q0 = Brow1[kb], q1 = Brow1[kb + 4];
                    mma_tf32(bc0, a0, a1, a2, a3, p0, p1);
                    mma_tf32(bc1, a0, a1, a2, a3, q0, q1);
                }
            }
#pragma unroll
            for (int q = 0; q < 4; q++) { ac0[q] += bc0[q]; ac1[q] += bc1[q]; }

            // ---- accumulators -> Gs ----
            int row = mt * 16 + g;
            int c0  = npair * 16 + 2 * t;
            *(float2*)(Gs + row * 66 + c0)           = make_float2(ac0[0], ac0[1]);
            *(float2*)(Gs + (row + 8) * 66 + c0)     = make_float2(ac0[2], ac0[3]);
            *(float2*)(Gs + row * 66 + c0 + 8)       = make_float2(ac1[0], ac1[1]);
            *(float2*)(Gs + (row + 8) * 66 + c0 + 8) = make_float2(ac1[2], ac1[3]);
            __syncthreads();
        }

        // ---- elementwise gates for 2 owned elements ----
        float gi0 = xi0, gf0 = xf0, gg0 = xg0, go0 = xo0;
        float gi1 = xi1, gf1 = xf1, gg1 = xg1, go1 = xo1;
        if (ts > 0) {
            const float* gr = Gs + er * 66;
            gi0 += gr[ej];          gi1 += gr[ej + 1];
            gf0 += gr[16 + ej];     gf1 += gr[16 + ej + 1];
            gg0 += gr[32 + ej];     gg1 += gr[32 + ej + 1];
            go0 += gr[48 + ej];     go1 += gr[48 + ej + 1];
        }
        float cp0 = Cs[e0], cp1 = Cs[e0 + 1];
        float i0 = sigmoidf_(gi0), f0 = sigmoidf_(gf0), gt0 = tanhf(gg0), o0 = sigmoidf_(go0);
        float i1 = sigmoidf_(gi1), f1 = sigmoidf_(gf1), gt1 = tanhf(gg1), o1 = sigmoidf_(go1);
        float cn0 = cp0 * f0 + i0 * gt0;
        float cn1 = cp1 * f1 + i1 * gt1;
        float h0 = o0 * tanhf(cn0);
        float h1 = o1 * tanhf(cn1);
        Cs[e0] = cn0; Cs[e0 + 1] = cn1;

        float* orow = out + (size_t)ts * (BATCH * HID) + (size_t)(b0 + er) * HID + j0;
        orow[ej]     = h0;
        orow[ej + 1] = h1;

        __threadfence();
        __syncthreads();

        // ---- grid barrier (skip after last step) ----
        if (ts < T_STEPS - 1) {
            if (tid == 0) {
                atomicAdd(&g_bar[ts], 1u);
                unsigned v;
                do {
                    v = *((volatile unsigned int*)&g_bar[ts]);
                } while (v < (unsigned)gridDim.x);
            }
            __syncthreads();
        }
    }

    // ---- exit: last block resets barrier state for the next graph replay ----
    __syncthreads();
    if (tid == 0) {
        unsigned old = atomicAdd(&g_exit, 1u);
        if (old == (unsigned)gridDim.x - 1u) {
            for (int i = 0; i < T_STEPS; i++) g_bar[i] = 0u;
            __threadfence();
            g_exit = 0u;
        }
    }
}

// ===========================================================================
// Launch
// ===========================================================================
extern "C" void kernel_launch(void* const* d_in, const int* in_sizes, int n_in,
                              void* d_out, int out_size)
{
    (void)in_sizes; (void)n_in; (void)out_size;
    const float* x  = (const float*)d_in[0];
    const float* Wx = (const float*)d_in[1];
    const float* bx = (const float*)d_in[2];
    const float* Wh = (const float*)d_in[3];
    const float* bh = (const float*)d_in[4];
    float* out = (float*)d_out;

    cudaFuncSetAttribute(lstm_rec_kernel,
                         cudaFuncAttributeMaxDynamicSharedMemorySize,
                         SMEM_B_BYTES);

    // Phase A: xg = x*Wx^T + bx + bh   (grid: 16 N-tiles x 512 M-tiles)
    gemm_xg_kernel<<<dim3(G4 / 128, (T_STEPS * BATCH) / 128), 256>>>(x, Wx, bx, bh);

    // Phase B: persistent recurrence (128 blocks, all SM-resident)
    lstm_rec_kernel<<<128, 256, SMEM_B_BYTES>>>(Wh, out);
}

// round 3
// speedup vs baseline: 1.1054x; 1.1054x over previous
#include <cuda_runtime.h>
#include <cstdint>
#include <cstddef>

// Problem constants (fixed by the dataset)
#define T_STEPS 512
#define BATCH   128
#define DIN     512
#define HID     512
#define G4      2048   // 4*HID

// ---------------------------------------------------------------------------
// Device-global scratch (allocation-free rule: __device__ arrays only).
// g_xg  : precomputed input projections, [T, B, 4H] fp32 (512 MB)
// g_bar : per-(bi-group, step) arrival counters (4 groups x 512 steps)
// g_exit: exit counter; last block resets barrier state for the next replay
// ---------------------------------------------------------------------------
__device__ float        g_xg[(size_t)T_STEPS * BATCH * G4];
__device__ unsigned int g_bar[4 * T_STEPS];
__device__ unsigned int g_exit;

// ---------------------------------------------------------------------------
// helpers
// ---------------------------------------------------------------------------
__device__ __forceinline__ uint32_t f2tf(float f) {
    uint32_t u;
    asm("cvt.rna.tf32.f32 %0, %1;" : "=r"(u) : "f"(f));
    return u;
}

// load fp32 from SMEM, round to tf32
__device__ __forceinline__ uint32_t ldcvt(const float* p) {
    uint32_t u;
    asm("cvt.rna.tf32.f32 %0, %1;" : "=r"(u) : "f"(*p));
    return u;
}

__device__ __forceinline__ void mma_tf32(float* d,
    uint32_t a0, uint32_t a1, uint32_t a2, uint32_t a3,
    uint32_t b0, uint32_t b1)
{
    asm volatile(
        "mma.sync.aligned.m16n8k8.row.col.f32.tf32.tf32.f32 "
        "{%0,%1,%2,%3}, {%4,%5,%6,%7}, {%8,%9}, {%0,%1,%2,%3};\n"
        : "+f"(d[0]), "+f"(d[1]), "+f"(d[2]), "+f"(d[3])
        : "r"(a0), "r"(a1), "r"(a2), "r"(a3), "r"(b0), "r"(b1));
}

__device__ __forceinline__ void cp16(uint32_t dst, const void* src) {
    asm volatile("cp.async.cg.shared.global [%0], [%1], 16;" :: "r"(dst), "l"(src));
}
__device__ __forceinline__ void cp_commit() {
    asm volatile("cp.async.commit_group;");
}
template <int N>
__device__ __forceinline__ void cp_wait() {
    asm volatile("cp.async.wait_group %0;" :: "n"(N));
}

__device__ __forceinline__ float fsigmoid(float x) {
    return __fdividef(1.0f, 1.0f + __expf(-x));
}
// tanh via exp: 2/(1+e^{-2x}) - 1. abs err ~1e-6, saturates correctly.
__device__ __forceinline__ float ftanh(float x) {
    float e = __expf(-2.0f * x);
    return __fdividef(2.0f, 1.0f + e) - 1.0f;
}

// ===========================================================================
// Phase A: xg[m][n] = sum_k x[m][k] * Wx[n][k] + bx[n] + bh[n]
//   M = 65536, N = 2048, K = 512. Block tile 128x128, BK=16, 256 threads.
//   2-stage cp.async pipeline; SMEM holds raw fp32 (stride 20); fragments
//   are rounded to tf32 at load time (identical numerics to pre-conversion).
// ===========================================================================
#define PA_W (128 * 20)                 // words per tile stage
#define SMEM_A_BYTES (4 * PA_W * 4)     // As0|As1|Bs0|Bs1 = 40960 B

__global__ __launch_bounds__(256, 2) void gemm_xg_kernel(
    const float* __restrict__ x,
    const float* __restrict__ Wx,
    const float* __restrict__ bxp,
    const float* __restrict__ bhp)
{
    extern __shared__ float smA[];
    float* Asb[2] = { smA,            smA + PA_W };
    float* Bsb[2] = { smA + 2 * PA_W, smA + 3 * PA_W };

    const int tid  = threadIdx.x;
    const int bn   = blockIdx.x * 128;
    const int bm   = blockIdx.y * 128;
    const int warp = tid >> 5;
    const int lane = tid & 31;
    const int wm   = (warp & 3) * 32;
    const int wn   = (warp >> 2) * 64;
    const int g    = lane >> 2;
    const int t    = lane & 3;

    const uint32_t sbase = (uint32_t)__cvta_generic_to_shared(smA);

    float acc[2][8][4];
#pragma unroll
    for (int i = 0; i < 2; i++)
#pragma unroll
        for (int j = 0; j < 8; j++)
#pragma unroll
            for (int q = 0; q < 4; q++) acc[i][j][q] = 0.0f;

    // per-thread load coordinates (2 float4 of A + 2 of B per stage)
    auto issue_stage = [&](int k0, int s) {
#pragma unroll
        for (int i = 0; i < 2; i++) {
            int id = i * 256 + tid;
            int r  = id >> 2;
            int c4 = id & 3;
            uint32_t dA = sbase + (uint32_t)((s * PA_W + r * 20 + c4 * 4) * 4);
            cp16(dA, x + (size_t)(bm + r) * DIN + k0 + c4 * 4);
            uint32_t dB = sbase + (uint32_t)(((2 + s) * PA_W + r * 20 + c4 * 4) * 4);
            cp16(dB, Wx + (size_t)(bn + r) * DIN + k0 + c4 * 4);
        }
        cp_commit();
    };

    issue_stage(0, 0);

    for (int it = 0; it < 32; it++) {
        if (it + 1 < 32) {
            issue_stage((it + 1) * 16, (it + 1) & 1);
            cp_wait<1>();
        } else {
            cp_wait<0>();
        }
        __syncthreads();

        const float* As = Asb[it & 1];
        const float* Bs = Bsb[it & 1];

#pragma unroll
        for (int kk = 0; kk < 2; kk++) {
            uint32_t a[2][4], b[8][2];
#pragma unroll
            for (int mt = 0; mt < 2; mt++) {
                int row = wm + mt * 16;
                a[mt][0] = ldcvt(As + (row + g    ) * 20 + kk * 8 + t);
                a[mt][1] = ldcvt(As + (row + g + 8) * 20 + kk * 8 + t);
                a[mt][2] = ldcvt(As + (row + g    ) * 20 + kk * 8 + t + 4);
                a[mt][3] = ldcvt(As + (row + g + 8) * 20 + kk * 8 + t + 4);
            }
#pragma unroll
            for (int nt = 0; nt < 8; nt++) {
                int col = wn + nt * 8 + g;
                b[nt][0] = ldcvt(Bs + col * 20 + kk * 8 + t);
                b[nt][1] = ldcvt(Bs + col * 20 + kk * 8 + t + 4);
            }
#pragma unroll
            for (int mt = 0; mt < 2; mt++)
#pragma unroll
                for (int nt = 0; nt < 8; nt++)
                    mma_tf32(acc[mt][nt],
                             a[mt][0], a[mt][1], a[mt][2], a[mt][3],
                             b[nt][0], b[nt][1]);
        }
        __syncthreads();
    }

    // epilogue: add biases, store
#pragma unroll
    for (int mt = 0; mt < 2; mt++) {
        int row0 = bm + wm + mt * 16 + g;
#pragma unroll
        for (int nt = 0; nt < 8; nt++) {
            int col = bn + wn + nt * 8 + 2 * t;
            float bias0 = bxp[col]     + bhp[col];
            float bias1 = bxp[col + 1] + bhp[col + 1];
            float2 v0 = make_float2(acc[mt][nt][0] + bias0, acc[mt][nt][1] + bias1);
            float2 v1 = make_float2(acc[mt][nt][2] + bias0, acc[mt][nt][3] + bias1);
            *(float2*)(g_xg + (size_t)row0 * G4 + col)       = v0;
            *(float2*)(g_xg + (size_t)(row0 + 8) * G4 + col) = v1;
        }
    }
}

// ===========================================================================
// Phase B: persistent recurrent kernel.
//   128 blocks = 4 bi-groups x 32 bj. Block owns 32 batch rows x 16 h-cols.
//   Wh slice (64 gate cols x 512, tf32) resident in SMEM.
//   Per step: cp.async h tile -> SMEM (fp32), tf32 GEMM (cvt at frag load),
//   gates, elementwise, store h to out[t], 32-wide release/acquire barrier
//   (cooperative-groups grid-sync pattern, scoped to the bi-group).
// ===========================================================================
#define WHS_WORDS (64 * 516)
#define HS_WORDS  (32 * 516)
#define GS_FLOATS (32 * 66)
#define CS_FLOATS (512)
#define SMEM_B_BYTES ((WHS_WORDS + HS_WORDS + GS_FLOATS + CS_FLOATS) * 4)

__global__ __launch_bounds__(256, 1) void lstm_rec_kernel(
    const float* __restrict__ Wh,
    float* __restrict__ out)
{
    extern __shared__ uint32_t smB[];
    uint32_t* Whs = smB;                                   // [64][516] tf32
    float*    Hs  = (float*)(smB + WHS_WORDS);             // [32][516] fp32
    float*    Gs  = (float*)(smB + WHS_WORDS + HS_WORDS);  // [32][66]
    float*    Cs  = Gs + GS_FLOATS;                        // [32][16]

    const int tid  = threadIdx.x;
    const int warp = tid >> 5;
    const int lane = tid & 31;
    const int g    = lane >> 2;
    const int t    = lane & 3;

    const int bi = blockIdx.x >> 5;
    const int bj = blockIdx.x & 31;
    const int b0 = bi * 32;
    const int j0 = bj * 16;

    // one-time: Wh slice -> SMEM (tf32), c = 0
    for (int idx = tid; idx < 64 * 512; idx += 256) {
        int c = idx >> 9;
        int k = idx & 511;
        int gcol = (c >> 4) * HID + j0 + (c & 15);
        Whs[c * 516 + k] = f2tf(Wh[(size_t)gcol * HID + k]);
    }
    for (int i = tid; i < CS_FLOATS; i += 256) Cs[i] = 0.0f;
    __syncthreads();

    const int mt    = warp & 1;
    const int npair = warp >> 1;

    const int e0 = tid * 2;
    const int er = e0 >> 4;
    const int ej = e0 & 15;

    const float*    Arow0 = Hs + (mt * 16 + g) * 516;
    const float*    Arow1 = Hs + (mt * 16 + g + 8) * 516;
    const uint32_t* Brow0 = Whs + (npair * 16 + g) * 516;
    const uint32_t* Brow1 = Whs + (npair * 16 + 8 + g) * 516;

    const uint32_t hs_sm = (uint32_t)__cvta_generic_to_shared(Hs);
    unsigned int* barp = g_bar + bi * T_STEPS;

    // prefetch xg[0]
    float xr[8];
    {
        const float* xgp = g_xg + ((size_t)b0 + er) * G4 + j0;
        xr[0] = xgp[ej];           xr[1] = xgp[ej + 1];
        xr[2] = xgp[HID + ej];     xr[3] = xgp[HID + ej + 1];
        xr[4] = xgp[2*HID + ej];   xr[5] = xgp[2*HID + ej + 1];
        xr[6] = xgp[3*HID + ej];   xr[7] = xgp[3*HID + ej + 1];
    }

    for (int ts = 0; ts < T_STEPS; ts++) {
        if (ts > 0) {
            // ---- h_{t-1} tile -> SMEM via cp.async (raw fp32) ----
            const float* hsrc = out + (size_t)(ts - 1) * (BATCH * HID) + (size_t)b0 * HID;
#pragma unroll
            for (int i = 0; i < 16; i++) {
                int id = i * 256 + tid;
                int r  = id >> 7;
                int k4 = id & 127;
                cp16(hs_sm + (uint32_t)((r * 516 + k4 * 4) * 4),
                     hsrc + r * HID + k4 * 4);
            }
            cp_commit();
            cp_wait<0>();
            __syncthreads();

            // ---- 32x64x512 tf32 GEMM (cvt A-frags at load) ----
            float ac0[4] = {0.f, 0.f, 0.f, 0.f};
            float ac1[4] = {0.f, 0.f, 0.f, 0.f};
            float bc0[4] = {0.f, 0.f, 0.f, 0.f};
            float bc1[4] = {0.f, 0.f, 0.f, 0.f};

#pragma unroll 2
            for (int kk = 0; kk < 64; kk += 2) {
                int kb = kk * 8 + t;
                {
                    uint32_t a0 = ldcvt(Arow0 + kb),     a1 = ldcvt(Arow1 + kb);
                    uint32_t a2 = ldcvt(Arow0 + kb + 4), a3 = ldcvt(Arow1 + kb + 4);
                    uint32_t p0 = Brow0[kb], p1 = Brow0[kb + 4];
                    uint32_t q0 = Brow1[kb], q1 = Brow1[kb + 4];
                    mma_tf32(ac0, a0, a1, a2, a3, p0, p1);
                    mma_tf32(ac1, a0, a1, a2, a3, q0, q1);
                }
                kb += 8;
                {
                    uint32_t a0 = ldcvt(Arow0 + kb),     a1 = ldcvt(Arow1 + kb);
                    uint32_t a2 = ldcvt(Arow0 + kb + 4), a3 = ldcvt(Arow1 + kb + 4);
                    uint32_t p0 = Brow0[kb], p1 = Brow0[kb + 4];
                    uint32_t q0 = Brow1[kb], q1 = Brow1[kb + 4];
                    mma_tf32(bc0, a0, a1, a2, a3, p0, p1);
                    mma_tf32(bc1, a0, a1, a2, a3, q0, q1);
                }
            }
#pragma unroll
            for (int q = 0; q < 4; q++) { ac0[q] += bc0[q]; ac1[q] += bc1[q]; }

            int row = mt * 16 + g;
            int c0  = npair * 16 + 2 * t;
            *(float2*)(Gs + row * 66 + c0)           = make_float2(ac0[0], ac0[1]);
            *(float2*)(Gs + (row + 8) * 66 + c0)     = make_float2(ac0[2], ac0[3]);
            *(float2*)(Gs + row * 66 + c0 + 8)       = make_float2(ac1[0], ac1[1]);
            *(float2*)(Gs + (row + 8) * 66 + c0 + 8) = make_float2(ac1[2], ac1[3]);
            __syncthreads();
        }

        // ---- elementwise gates ----
        float gi0 = xr[0], gi1 = xr[1];
        float gf0 = xr[2], gf1 = xr[3];
        float gg0 = xr[4], gg1 = xr[5];
        float go0 = xr[6], go1 = xr[7];
        if (ts > 0) {
            const float* gr = Gs + er * 66;
            gi0 += gr[ej];        gi1 += gr[ej + 1];
            gf0 += gr[16 + ej];   gf1 += gr[16 + ej + 1];
            gg0 += gr[32 + ej];   gg1 += gr[32 + ej + 1];
            go0 += gr[48 + ej];   go1 += gr[48 + ej + 1];
        }
        float cp0 = Cs[e0], cp1 = Cs[e0 + 1];
        float i0 = fsigmoid(gi0), f0 = fsigmoid(gf0), gt0 = ftanh(gg0), o0 = fsigmoid(go0);
        float i1 = fsigmoid(gi1), f1 = fsigmoid(gf1), gt1 = ftanh(gg1), o1 = fsigmoid(go1);
        float cn0 = cp0 * f0 + i0 * gt0;
        float cn1 = cp1 * f1 + i1 * gt1;
        float h0 = o0 * ftanh(cn0);
        float h1 = o1 * ftanh(cn1);
        Cs[e0] = cn0; Cs[e0 + 1] = cn1;

        float* orow = out + (size_t)ts * (BATCH * HID) + (size_t)(b0 + er) * HID + j0;
        *(float2*)(orow + ej) = make_float2(h0, h1);

        __syncthreads();   // all h stores issued before the release-arrive

        if (ts < T_STEPS - 1) {
            // prefetch xg[ts+1] (independent of barrier; hides LDG latency)
            const float* xgp = g_xg + ((size_t)(ts + 1) * BATCH + b0 + er) * G4 + j0;
            xr[0] = xgp[ej];           xr[1] = xgp[ej + 1];
            xr[2] = xgp[HID + ej];     xr[3] = xgp[HID + ej + 1];
            xr[4] = xgp[2*HID + ej];   xr[5] = xgp[2*HID + ej + 1];
            xr[6] = xgp[3*HID + ej];   xr[7] = xgp[3*HID + ej + 1];

            // ---- 32-wide release/acquire barrier (bi-group only) ----
            if (tid == 0) {
                unsigned int* p = barp + ts;
                unsigned old;
                asm volatile("atom.acq_rel.gpu.add.u32 %0, [%1], 1;"
                             : "=r"(old) : "l"(p) : "memory");
                if (old != 31u) {
                    unsigned v;
                    do {
                        __nanosleep(32);   // backoff: keep L2 atomic slice clear
                        asm volatile("ld.acquire.gpu.u32 %0, [%1];"
                                     : "=r"(v) : "l"(p) : "memory");
                    } while (v < 32u);
                }
            }
            __syncthreads();
        }
    }

    // ---- exit: last block resets barrier state for the next graph replay ----
    __syncthreads();
    if (tid == 0) {
        unsigned old;
        asm volatile("atom.acq_rel.gpu.add.u32 %0, [%1], 1;"
                     : "=r"(old) : "l"(&g_exit) : "memory");
        Gs[0] = (old == 127u) ? 1.0f : 0.0f;
    }
    __syncthreads();
    if (Gs[0] != 0.0f) {
        for (int i = tid; i < 4 * T_STEPS; i += 256) g_bar[i] = 0u;
        __threadfence();
        if (tid == 0) g_exit = 0u;
    }
}

// ===========================================================================
// Launch
// ===========================================================================
extern "C" void kernel_launch(void* const* d_in, const int* in_sizes, int n_in,
                              void* d_out, int out_size)
{
    (void)in_sizes; (void)n_in; (void)out_size;
    const float* x  = (const float*)d_in[0];
    const float* Wx = (const float*)d_in[1];
    const float* bx = (const float*)d_in[2];
    const float* Wh = (const float*)d_in[3];
    const float* bh = (const float*)d_in[4];
    float* out = (float*)d_out;

    cudaFuncSetAttribute(gemm_xg_kernel,
                         cudaFuncAttributeMaxDynamicSharedMemorySize,
                         SMEM_A_BYTES);
    cudaFuncSetAttribute(lstm_rec_kernel,
                         cudaFuncAttributeMaxDynamicSharedMemorySize,
                         SMEM_B_BYTES);

    gemm_xg_kernel<<<dim3(G4 / 128, (T_STEPS * BATCH) / 128), 256, SMEM_A_BYTES>>>(x, Wx, bx, bh);
    lstm_rec_kernel<<<128, 256, SMEM_B_BYTES>>>(Wh, out);
}